// round 1
// baseline (speedup 1.0000x reference)
#include <cuda_runtime.h>

#define B_    2048
#define FS_   32
#define FA_   16
#define T_    512
#define H_    64
#define SIN_  48            // FA + FS
#define KP1_  24            // layer1 k-pairs (48/2)
#define KP2_  32            // layer2 k-pairs (64/2)
#define SQRT_DT_ 0.22360679774997896f
#define MIN_V_  (-5.0f)
#define MAX_V_  (5.0f)

typedef unsigned long long u64;

__device__ __forceinline__ u64 pack2(float lo, float hi) {
    u64 r; asm("mov.b64 %0, {%1, %2};" : "=l"(r) : "f"(lo), "f"(hi)); return r;
}
__device__ __forceinline__ float2 unpack2(u64 v) {
    float2 f; asm("mov.b64 {%0, %1}, %2;" : "=f"(f.x), "=f"(f.y) : "l"(v)); return f;
}
// packed dual fp32 FMA (sm_100+): 2 fp32 FLOPs per issue slot on the FMA pipe
__device__ __forceinline__ u64 ffma2(u64 a, u64 b, u64 c) {
    u64 d; asm("fma.rn.f32x2 %0, %1, %2, %3;" : "=l"(d) : "l"(a), "l"(b), "l"(c)); return d;
}
// accurate-enough tanh: ex2.approx (~2^-22) + rcp.approx (~2^-23); abs err ~1e-7
// (tanh.approx.f32 is only ~2^-11 -- too coarse for a 511-step recurrence)
__device__ __forceinline__ float tanh_acc(float x) {
    float e, r;
    asm("ex2.approx.f32 %0, %1;" : "=f"(e) : "f"(x * 2.8853900817779268f)); // 2*log2(e)
    asm("rcp.approx.f32 %0, %1;" : "=f"(r) : "f"(e + 1.0f));
    return (e - 1.0f) * r;
}

// One batch element per block (64 threads). warp0 = f-MLP (+state update),
// warp1 = g-MLP (+noise). Weights live in registers as f32x2 pairs over k.
__global__ void __launch_bounds__(64)
sde_kernel(const float* __restrict__ a_in,   // (B, FA, T)
           const float* __restrict__ x0,     // (B, FS)
           const float* __restrict__ noise,  // (T-1, B, FS)
           const float* __restrict__ Wf1, const float* __restrict__ bf1,
           const float* __restrict__ Wf2, const float* __restrict__ bf2,
           const float* __restrict__ Wg1, const float* __restrict__ bg1,
           const float* __restrict__ Wg2, const float* __restrict__ bg2,
           float* __restrict__ out)          // (B, FS, T)
{
    const int b    = blockIdx.x;
    const int wid  = threadIdx.x >> 5;   // 0 = f, 1 = g
    const int lane = threadIdx.x & 31;

    __shared__ __align__(16) float s_sm[64];      // [0,16)=a_t, [16,48)=x_t, rest pad
    __shared__ __align__(16) float h_sm[2][64];   // per-warp hidden exchange
    __shared__ float d_sm[32];                    // diffusion term exchange

    const float* W1 = wid ? Wg1 : Wf1;
    const float* b1 = wid ? bg1 : bf1;
    const float* W2 = wid ? Wg2 : Wf2;
    const float* b2 = wid ? bg2 : bf2;

    // -------- load weights into registers, packed over (k, k+1) pairs --------
    u64 w1a[KP1_], w1b[KP1_], w2p[KP2_];
#pragma unroll
    for (int kp = 0; kp < KP1_; kp++) {
        w1a[kp] = pack2(W1[(2*kp)*H_ + lane],      W1[(2*kp+1)*H_ + lane]);
        w1b[kp] = pack2(W1[(2*kp)*H_ + lane + 32], W1[(2*kp+1)*H_ + lane + 32]);
    }
#pragma unroll
    for (int kp = 0; kp < KP2_; kp++) {
        w2p[kp] = pack2(W2[(2*kp)*FS_ + lane], W2[(2*kp+1)*FS_ + lane]);
    }
    const float bias1a = b1[lane];
    const float bias1b = b1[lane + 32];
    const float bias2  = b2[lane];

    // -------- prologue: stage s = [a_0, x_0], write out[..., 0] --------
    if (wid == 0) {
        if (lane < FA_) s_sm[lane] = a_in[(size_t)b * FA_ * T_ + (size_t)lane * T_];
        float x = x0[(size_t)b * FS_ + lane];
        s_sm[16 + lane] = x;
        out[(size_t)b * FS_ * T_ + (size_t)lane * T_] = x;
    }
    __syncthreads();

    const float* noise_b = noise + (size_t)b * FS_ + lane;                 // +t*B*FS per step
    float*       out_b   = out   + (size_t)b * FS_ * T_ + (size_t)lane * T_;
    const float* a_b     = a_in  + (size_t)b * FA_ * T_ + (size_t)lane * T_; // deref only lane<16

#pragma unroll 1
    for (int t = 1; t < T_; t++) {
        // g-warp: noise for this step (issued early to hide latency under layer1/2)
        float eps = 0.0f;
        if (wid == 1) eps = noise_b[(size_t)(t - 1) * (B_ * FS_)];

        // read s as 24 packed pairs (broadcast LDS.128, conflict-free)
        u64 sp[KP1_];
#pragma unroll
        for (int q = 0; q < 12; q++) {
            ulonglong2 v = reinterpret_cast<const ulonglong2*>(s_sm)[q];
            sp[2*q] = v.x; sp[2*q+1] = v.y;
        }

        // ---- layer 1: h[lane], h[lane+32]; 4 independent accumulator chains ----
        u64 aa0 = 0ull, aa1 = 0ull, ab0 = 0ull, ab1 = 0ull;
#pragma unroll
        for (int kp = 0; kp < KP1_; kp += 2) {
            aa0 = ffma2(sp[kp],     w1a[kp],     aa0);
            ab0 = ffma2(sp[kp],     w1b[kp],     ab0);
            aa1 = ffma2(sp[kp + 1], w1a[kp + 1], aa1);
            ab1 = ffma2(sp[kp + 1], w1b[kp + 1], ab1);
        }
        {
            float2 u0 = unpack2(aa0), u1 = unpack2(aa1);
            float2 v0 = unpack2(ab0), v1 = unpack2(ab1);
            float ha = tanh_acc((u0.x + u0.y) + (u1.x + u1.y) + bias1a);
            float hb = tanh_acc((v0.x + v0.y) + (v1.x + v1.y) + bias1b);
            h_sm[wid][lane]      = ha;
            h_sm[wid][lane + 32] = hb;
        }
        __syncwarp();

        // ---- layer 2: out[lane] over k=0..63 (32 pairs, 2 chains) ----
        u64 hp[KP2_];
#pragma unroll
        for (int q = 0; q < 16; q++) {
            ulonglong2 v = reinterpret_cast<const ulonglong2*>(h_sm[wid])[q];
            hp[2*q] = v.x; hp[2*q+1] = v.y;
        }
        u64 c0 = 0ull, c1 = 0ull;
#pragma unroll
        for (int kp = 0; kp < KP2_; kp += 2) {
            c0 = ffma2(hp[kp],     w2p[kp],     c0);
            c1 = ffma2(hp[kp + 1], w2p[kp + 1], c1);
        }
        float2 e0 = unpack2(c0), e1 = unpack2(c1);
        float o = (e0.x + e0.y) + (e1.x + e1.y) + bias2;

        // g-warp publishes diffusion term
        if (wid == 1) d_sm[lane] = o * (eps * SQRT_DT_);
        __syncthreads();

        // f-warp: state update, output store, stage next step's s
        if (wid == 0) {
            float x = o + d_sm[lane];
            x = fminf(fmaxf(x, MIN_V_), MAX_V_);
            s_sm[16 + lane] = x;
            out_b[t] = x;
            if (lane < FA_) s_sm[lane] = a_b[t];   // a_t feeds iteration t+1
        }
        __syncthreads();
    }
}

extern "C" void kernel_launch(void* const* d_in, const int* in_sizes, int n_in,
                              void* d_out, int out_size) {
    (void)in_sizes; (void)n_in; (void)out_size;
    // metadata order: ts, in_signal, x0, noise, Wf1, bf1, Wf2, bf2, Wg1, bg1, Wg2, bg2
    const float* a_in  = (const float*)d_in[1];
    const float* x0    = (const float*)d_in[2];
    const float* noise = (const float*)d_in[3];
    const float* Wf1   = (const float*)d_in[4];
    const float* bf1   = (const float*)d_in[5];
    const float* Wf2   = (const float*)d_in[6];
    const float* bf2   = (const float*)d_in[7];
    const float* Wg1   = (const float*)d_in[8];
    const float* bg1   = (const float*)d_in[9];
    const float* Wg2   = (const float*)d_in[10];
    const float* bg2   = (const float*)d_in[11];
    float* out = (float*)d_out;

    sde_kernel<<<B_, 64>>>(a_in, x0, noise,
                           Wf1, bf1, Wf2, bf2,
                           Wg1, bg1, Wg2, bg2,
                           out);
}

// round 2
// speedup vs baseline: 1.5718x; 1.5718x over previous
#include <cuda_runtime.h>

#define B_    2048
#define FS_   32
#define FA_   16
#define T_    512
#define H_    64
#define SQRT_DT_ 0.22360679774997896f
#define MIN_V_  (-5.0f)
#define MAX_V_  (5.0f)

typedef unsigned long long u64;

__device__ __forceinline__ u64 pack2(float lo, float hi) {
    u64 r; asm("mov.b64 %0, {%1, %2};" : "=l"(r) : "f"(lo), "f"(hi)); return r;
}
__device__ __forceinline__ float2 unpack2(u64 v) {
    float2 f; asm("mov.b64 {%0, %1}, %2;" : "=f"(f.x), "=f"(f.y) : "l"(v)); return f;
}
// packed dual fp32 FMA (sm_100+): 2 fp32 FMAs per issue slot
__device__ __forceinline__ u64 ffma2(u64 a, u64 b, u64 c) {
    u64 d; asm("fma.rn.f32x2 %0, %1, %2, %3;" : "=l"(d) : "l"(a), "l"(b), "l"(c)); return d;
}
// accurate tanh from ex2.approx + rcp.approx (~1e-7 abs err)
__device__ __forceinline__ float tanh_acc(float x) {
    float e, r;
    asm("ex2.approx.f32 %0, %1;" : "=f"(e) : "f"(x * 2.8853900817779268f)); // 2*log2(e)
    asm("rcp.approx.f32 %0, %1;" : "=f"(r) : "f"(e + 1.0f));
    return (e - 1.0f) * r;
}

// Block = 256 threads = 8 warps = 4 (f,g) warp-pairs; each pair owns 4 batch
// elements => 16 elements per block, grid = 128 blocks (single wave on 148 SMs).
// Each warp holds its MLP's weights in registers as f32x2 pairs over k and
// processes 4 batch elements per step (8 independent FMA chains).
__global__ void __launch_bounds__(256, 1)
sde_kernel(const float* __restrict__ a_in,   // (B, FA, T)
           const float* __restrict__ x0,     // (B, FS)
           const float* __restrict__ noise,  // (T-1, B, FS)
           const float* __restrict__ Wf1, const float* __restrict__ bf1,
           const float* __restrict__ Wf2, const float* __restrict__ bf2,
           const float* __restrict__ Wg1, const float* __restrict__ bg1,
           const float* __restrict__ Wg2, const float* __restrict__ bg2,
           float* __restrict__ out)          // (B, FS, T)
{
    const int tid  = threadIdx.x;
    const int wid  = tid >> 5;
    const int lane = tid & 31;
    const int pair = wid >> 1;            // 0..3
    const bool is_g = (wid & 1) != 0;     // odd warp = g-MLP
    const int el0  = pair * 4;            // element slot base within block
    const int gb0  = blockIdx.x * 16 + el0;

    // ping-pong state x_t, double-buffered a-tiles (4 steps, transposed),
    // per-warp hidden exchange, diffusion exchange
    __shared__ __align__(16) float x_sm[2][16][32];      // 4 KB
    __shared__ __align__(16) float a_sg[2][16][4][16];   // 8 KB
    __shared__ __align__(16) float h_sm[8][4][64];       // 8 KB
    __shared__ float d_sm[16][32];                       // 2 KB

    const float* W1 = is_g ? Wg1 : Wf1;
    const float* b1 = is_g ? bg1 : bf1;
    const float* W2 = is_g ? Wg2 : Wf2;
    const float* b2 = is_g ? bg2 : bf2;

    // -------- register-resident weights, packed (k, k+1) over k --------
    u64 w1a[24], w1b[24], w2p[32];
#pragma unroll
    for (int kp = 0; kp < 24; kp++) {
        w1a[kp] = pack2(W1[(2*kp)*H_ + lane],      W1[(2*kp+1)*H_ + lane]);
        w1b[kp] = pack2(W1[(2*kp)*H_ + lane + 32], W1[(2*kp+1)*H_ + lane + 32]);
    }
#pragma unroll
    for (int kp = 0; kp < 32; kp++) {
        w2p[kp] = pack2(W2[(2*kp)*FS_ + lane], W2[(2*kp+1)*FS_ + lane]);
    }
    const float bias1a = b1[lane];
    const float bias1b = b1[lane + 32];
    const float bias2  = b2[lane];

    // per-warp global pointers (element e = base + e*stride)
    const float* a_base  = a_in  + (size_t)gb0 * (FA_ * T_) + (size_t)(lane >> 1) * T_ + (lane & 1) * 2;
    const float* nz_base = noise + (size_t)gb0 * FS_ + lane;
    float*       out_b   = out   + (size_t)gb0 * (FS_ * T_) + (size_t)lane * T_;

    float2 areg[4];    // prefetched a-tile (f warp)
    float  eps_n[4];   // next-step noise (g warp)

    if (!is_g) {
        // x0 -> state buffer 0, out[...,0]
#pragma unroll
        for (int e = 0; e < 4; e++) {
            float x = x0[(size_t)(gb0 + e) * FS_ + lane];
            x_sm[0][el0 + e][lane] = x;
            out_b[(size_t)e * (FS_ * T_)] = x;
        }
        // a group 0 (a-idx 0..3): LDG + transposed STS into buffer 0
#pragma unroll
        for (int e = 0; e < 4; e++)
            areg[e] = *reinterpret_cast<const float2*>(a_base + (size_t)e * (FA_ * T_));
#pragma unroll
        for (int e = 0; e < 4; e++) {
            a_sg[0][el0 + e][(lane & 1) * 2 + 0][lane >> 1] = areg[e].x;
            a_sg[0][el0 + e][(lane & 1) * 2 + 1][lane >> 1] = areg[e].y;
        }
        // a group 1 (a-idx 4..7) -> regs, STS'd in-loop
#pragma unroll
        for (int e = 0; e < 4; e++)
            areg[e] = *reinterpret_cast<const float2*>(a_base + (size_t)e * (FA_ * T_) + 4);
    } else {
        // noise for ai = 0
#pragma unroll
        for (int e = 0; e < 4; e++) eps_n[e] = nz_base[e * FS_];
    }
    __syncthreads();

    const int bar_id = 1 + pair;   // named barrier per warp-pair

#pragma unroll 1
    for (int t = 1; t < T_; t++) {
        const int ai  = t - 1;
        const int g4  = ai >> 2;
        const int buf = g4 & 1;
        const int sl  = ai & 3;

        // g: rotate noise double-buffer, issue next load early
        float eps_u[4];
        if (is_g) {
#pragma unroll
            for (int e = 0; e < 4; e++) eps_u[e] = eps_n[e];
            if (t < T_ - 1) {
                const float* np = nz_base + (size_t)t * (B_ * FS_);
#pragma unroll
                for (int e = 0; e < 4; e++) eps_n[e] = np[e * FS_];
            }
        }

        // ---------------- layer 1 (48 -> 64), 8 chains ----------------
        u64 aa[4], ab[4];
#pragma unroll
        for (int e = 0; e < 4; e++) { aa[e] = 0ull; ab[e] = 0ull; }

        // a-part: k = 0..15 (pairs 0..7)
#pragma unroll
        for (int q = 0; q < 4; q++) {
            const u64 wA0 = w1a[2*q], wA1 = w1a[2*q+1];
            const u64 wB0 = w1b[2*q], wB1 = w1b[2*q+1];
#pragma unroll
            for (int e = 0; e < 4; e++) {
                ulonglong2 v = *reinterpret_cast<const ulonglong2*>(&a_sg[buf][el0 + e][sl][4*q]);
                aa[e] = ffma2(v.x, wA0, aa[e]);
                aa[e] = ffma2(v.y, wA1, aa[e]);
                ab[e] = ffma2(v.x, wB0, ab[e]);
                ab[e] = ffma2(v.y, wB1, ab[e]);
            }
        }
        // x-part: k = 16..47 (pairs 8..23)
        {
            const int pb = ai & 1;
#pragma unroll
            for (int q = 0; q < 8; q++) {
                const u64 wA0 = w1a[8 + 2*q], wA1 = w1a[9 + 2*q];
                const u64 wB0 = w1b[8 + 2*q], wB1 = w1b[9 + 2*q];
#pragma unroll
                for (int e = 0; e < 4; e++) {
                    ulonglong2 v = *reinterpret_cast<const ulonglong2*>(&x_sm[pb][el0 + e][4*q]);
                    aa[e] = ffma2(v.x, wA0, aa[e]);
                    aa[e] = ffma2(v.y, wA1, aa[e]);
                    ab[e] = ffma2(v.x, wB0, ab[e]);
                    ab[e] = ffma2(v.y, wB1, ab[e]);
                }
            }
        }
        // tanh + publish h (warp-private)
#pragma unroll
        for (int e = 0; e < 4; e++) {
            float2 u = unpack2(aa[e]);
            float2 v = unpack2(ab[e]);
            h_sm[wid][e][lane]      = tanh_acc(u.x + u.y + bias1a);
            h_sm[wid][e][lane + 32] = tanh_acc(v.x + v.y + bias1b);
        }
        __syncwarp();

        // ---------------- layer 2 (64 -> 32), 8 chains ----------------
        u64 c0[4], c1[4];
#pragma unroll
        for (int e = 0; e < 4; e++) { c0[e] = 0ull; c1[e] = 0ull; }
#pragma unroll
        for (int q = 0; q < 16; q++) {
            const u64 w0 = w2p[2*q], w1x = w2p[2*q+1];
#pragma unroll
            for (int e = 0; e < 4; e++) {
                ulonglong2 v = *reinterpret_cast<const ulonglong2*>(&h_sm[wid][e][4*q]);
                c0[e] = ffma2(v.x, w0,  c0[e]);
                c1[e] = ffma2(v.y, w1x, c1[e]);
            }
        }
        float o[4];
#pragma unroll
        for (int e = 0; e < 4; e++) {
            float2 u = unpack2(c0[e]);
            float2 v = unpack2(c1[e]);
            o[e] = (u.x + u.y) + (v.x + v.y) + bias2;
        }

        // g publishes diffusion
        if (is_g) {
#pragma unroll
            for (int e = 0; e < 4; e++)
                d_sm[el0 + e][lane] = o[e] * (eps_u[e] * SQRT_DT_);
        }
        asm volatile("bar.sync %0, 64;" :: "r"(bar_id) : "memory");

        // f: state update + output + a-tile prefetch machinery
        if (!is_g) {
#pragma unroll
            for (int e = 0; e < 4; e++) {
                float x = o[e] + d_sm[el0 + e][lane];
                x = fminf(fmaxf(x, MIN_V_), MAX_V_);
                x_sm[t & 1][el0 + e][lane] = x;
                out_b[(size_t)e * (FS_ * T_) + t] = x;
            }
            if (sl == 2 && g4 + 1 < 128) {      // STS group g4+1 into buf^1
#pragma unroll
                for (int e = 0; e < 4; e++) {
                    a_sg[buf ^ 1][el0 + e][(lane & 1) * 2 + 0][lane >> 1] = areg[e].x;
                    a_sg[buf ^ 1][el0 + e][(lane & 1) * 2 + 1][lane >> 1] = areg[e].y;
                }
            }
            if (sl == 3 && g4 + 2 < 128) {      // LDG group g4+2 (~3 steps ahead)
                const float* ap = a_base + (size_t)(g4 + 2) * 4;
#pragma unroll
                for (int e = 0; e < 4; e++)
                    areg[e] = *reinterpret_cast<const float2*>(ap + (size_t)e * (FA_ * T_));
            }
        }
        asm volatile("bar.sync %0, 64;" :: "r"(bar_id) : "memory");
    }
}

extern "C" void kernel_launch(void* const* d_in, const int* in_sizes, int n_in,
                              void* d_out, int out_size) {
    (void)in_sizes; (void)n_in; (void)out_size;
    // metadata order: ts, in_signal, x0, noise, Wf1, bf1, Wf2, bf2, Wg1, bg1, Wg2, bg2
    const float* a_in  = (const float*)d_in[1];
    const float* x0    = (const float*)d_in[2];
    const float* noise = (const float*)d_in[3];
    const float* Wf1   = (const float*)d_in[4];
    const float* bf1   = (const float*)d_in[5];
    const float* Wf2   = (const float*)d_in[6];
    const float* bf2   = (const float*)d_in[7];
    const float* Wg1   = (const float*)d_in[8];
    const float* bg1   = (const float*)d_in[9];
    const float* Wg2   = (const float*)d_in[10];
    const float* bg2   = (const float*)d_in[11];
    float* out = (float*)d_out;

    sde_kernel<<<B_ / 16, 256>>>(a_in, x0, noise,
                                 Wf1, bf1, Wf2, bf2,
                                 Wg1, bg1, Wg2, bg2,
                                 out);
}